// round 14
// baseline (speedup 1.0000x reference)
#include <cuda_runtime.h>
#include <cstdint>
#include <cstddef>

// ---------------- problem constants ----------------
#define B_   2
#define N_   1569
#define C_   768
#define H_   12
#define D_   64
#define P_   196
#define F_   8
#define S_   1568          // F_*P_ = N_-1
#define C3_  2304          // 3*C_
#define BS_  (B_*S_)       // 3136
#define SCALE 0.125f       // d^-0.5 = 1/8

// ---------------- scratch (device globals) ----------------
__device__ float g_qkv  [B_*N_*C3_];
__device__ float g_traj [B_*S_*F_*C_];   // tf32-rounded
__device__ float g_q2   [B_*S_*C_];      // tf32-rounded (GEMM epilogue)
__device__ float g_u    [BS_*H_*C_];     // u[bs][h*C+c]
__device__ float g_attin[B_*N_*C_];      // tf32-rounded
__device__ float g_xr    [B_*N_*C_];
__device__ float g_wqkvr [C_*C3_];
__device__ float g_wpqr  [C_*C_];
__device__ float g_wkT   [C_*C_];
__device__ float g_wprojr[C_*C_];

// ---------------- helpers ----------------
__device__ __forceinline__ uint32_t f2tf32(float f) {
    uint32_t o;
    asm("cvt.rna.tf32.f32 %0, %1;" : "=r"(o) : "f"(f));
    return o;
}
__device__ __forceinline__ float roundtf32(float f) {
    return __uint_as_float(f2tf32(f));
}
__device__ __forceinline__ void cp16(void* dst, const void* src, bool p) {
    uint32_t d = (uint32_t)__cvta_generic_to_shared(dst);
    int sz = p ? 16 : 0;
    asm volatile("cp.async.ca.shared.global [%0], [%1], 16, %2;"
                 :: "r"(d), "l"(src), "r"(sz));
}
__device__ __forceinline__ void cp_commit() {
    asm volatile("cp.async.commit_group;");
}
__device__ __forceinline__ void mma_tf32(float* c,
    uint32_t a0, uint32_t a1, uint32_t a2, uint32_t a3,
    uint32_t b0, uint32_t b1)
{
    asm volatile(
        "mma.sync.aligned.m16n8k8.row.col.f32.tf32.tf32.f32 "
        "{%0,%1,%2,%3}, {%4,%5,%6,%7}, {%8,%9}, {%0,%1,%2,%3};"
        : "+f"(c[0]), "+f"(c[1]), "+f"(c[2]), "+f"(c[3])
        : "r"(a0), "r"(a1), "r"(a2), "r"(a3), "r"(b0), "r"(b1));
}
// ldmatrix x4: reg i <- 8x8 matrix i; lane l of matrix = (row l/4, word l%4)
__device__ __forceinline__ void ldsm_x4(uint32_t& r0, uint32_t& r1,
                                        uint32_t& r2, uint32_t& r3, uint32_t addr)
{
    asm volatile("ldmatrix.sync.aligned.m8n8.x4.shared.b16 {%0,%1,%2,%3}, [%4];"
                 : "=r"(r0), "=r"(r1), "=r"(r2), "=r"(r3) : "r"(addr));
}

// ======================================================================
// Pre-pass: round to tf32 (rna). n % 4 == 0.
// ======================================================================
__global__ __launch_bounds__(256) void round_tf32_kernel(
    const float* __restrict__ src, float* __restrict__ dst, int n)
{
    int i = (blockIdx.x * 256 + threadIdx.x) * 4;
    if (i >= n) return;
    float4 v = *(const float4*)(src + i);
    v.x = roundtf32(v.x); v.y = roundtf32(v.y);
    v.z = roundtf32(v.z); v.w = roundtf32(v.w);
    *(float4*)(dst + i) = v;
}

// ======================================================================
// Transpose + round: WkT[c'][c] = W_pkv[c][c'].
// ======================================================================
__global__ __launch_bounds__(256) void transpose_round_kernel(
    const float* __restrict__ src, float* __restrict__ dst)
{
    __shared__ float tile[32][33];
    int x0 = blockIdx.x * 32;
    int y0 = blockIdx.y * 32;
    #pragma unroll
    for (int i = 0; i < 4; i++) {
        int y = y0 + threadIdx.y + i * 8;
        tile[threadIdx.y + i * 8][threadIdx.x] =
            roundtf32(src[(size_t)y * (2 * C_) + x0 + threadIdx.x]);
    }
    __syncthreads();
    #pragma unroll
    for (int i = 0; i < 4; i++) {
        int yo = x0 + threadIdx.y + i * 8;
        dst[(size_t)yo * C_ + y0 + threadIdx.x] =
            tile[threadIdx.x][threadIdx.y + i * 8];
    }
}

// ======================================================================
// TF32 GEMM, cp.async double buffered; A-fragments via ldmatrix.x4.
// ======================================================================
#define GEMM_SMEM_BYTES ((2*128*36 + 2*32*136) * 4)

__global__ __launch_bounds__(256, 2) void gemm_tf32_db(
    const float* __restrict__ A, int lda,
    const float* __restrict__ Bw, int ldb,
    float* __restrict__ Cc, int ldc,
    int M, int K, float alpha, const float* __restrict__ bias, int flags,
    int zsa, size_t zsb, size_t zsc)
{
    extern __shared__ float gsm[];
    float* As = gsm;                 // [2][128*36]
    float* Bs = gsm + 2 * 128 * 36;  // [2][32*136]

    A  += (size_t)blockIdx.z * zsa;
    Bw += (size_t)blockIdx.z * zsb;
    Cc += (size_t)blockIdx.z * zsc;

    const int tid    = threadIdx.x;
    const int warp   = tid >> 5;
    const int lane   = tid & 31;
    const int g      = lane >> 2;
    const int t      = lane & 3;
    const int warp_m = warp >> 2;
    const int warp_n = warp & 3;
    const int row0   = blockIdx.y * 128;
    const int col0   = blockIdx.x * 128;
    const bool diag  = flags & 1;
    const bool rndo  = flags & 2;

    // ldmatrix addressing for A: row = lane&15, col-half = lane>>4
    const uint32_t a_smem0 = (uint32_t)__cvta_generic_to_shared(As);
    const int arow = lane & 15;
    const int acol = (lane >> 4) * 4;

    float acc[4][4][4];
    #pragma unroll
    for (int mt = 0; mt < 4; mt++)
        #pragma unroll
        for (int nt = 0; nt < 4; nt++)
            #pragma unroll
            for (int r = 0; r < 4; r++) acc[mt][nt][r] = 0.f;

    const int ntiles = K / 32;

    auto issue_tile = [&](int buf, int k0) {
        float* Ab = As + buf * 128 * 36;
        float* Bb = Bs + buf * 32 * 136;
        #pragma unroll
        for (int i = 0; i < 4; i++) {
            int idx = tid + i * 256;
            int r   = idx >> 3;
            int c   = (idx & 7) * 4;
            int gr  = row0 + r;
            const float* src;
            if (diag) {
                int s = gr % S_;
                src = A + ((size_t)gr * F_ + (s / P_)) * C_ + k0 + c;
            } else {
                src = A + (size_t)gr * lda + k0 + c;
            }
            cp16(Ab + r * 36 + c, src, gr < M);
        }
        #pragma unroll
        for (int i = 0; i < 4; i++) {
            int idx = tid + i * 256;
            int r   = idx >> 5;
            int c   = (idx & 31) * 4;
            cp16(Bb + r * 136 + c, Bw + (size_t)(k0 + r) * ldb + col0 + c, true);
        }
        cp_commit();
    };

    issue_tile(0, 0);

    for (int kt = 0; kt < ntiles; kt++) {
        int cur = kt & 1;
        if (kt + 1 < ntiles) {
            issue_tile(cur ^ 1, (kt + 1) * 32);
            asm volatile("cp.async.wait_group 1;");
        } else {
            asm volatile("cp.async.wait_group 0;");
        }
        __syncthreads();

        const uint32_t* Bb = (const uint32_t*)(Bs + cur * 32 * 136);
        const uint32_t a_base = a_smem0 + (uint32_t)(cur * 128 * 36) * 4u;

        #pragma unroll
        for (int kk = 0; kk < 32; kk += 8) {
            uint32_t a[4][4], bf[4][2];
            #pragma unroll
            for (int mt = 0; mt < 4; mt++) {
                uint32_t addr = a_base +
                    (uint32_t)(((warp_m * 64 + mt * 16 + arow) * 36 + acol + kk) * 4);
                ldsm_x4(a[mt][0], a[mt][1], a[mt][2], a[mt][3], addr);
            }
            #pragma unroll
            for (int nt = 0; nt < 4; nt++) {
                int c = warp_n * 32 + nt * 8 + g;
                const uint32_t* p = &Bb[(kk + t) * 136 + c];
                bf[nt][0] = p[0];
                bf[nt][1] = p[4 * 136];
            }
            #pragma unroll
            for (int mt = 0; mt < 4; mt++)
                #pragma unroll
                for (int nt = 0; nt < 4; nt++)
                    mma_tf32(acc[mt][nt], a[mt][0], a[mt][1], a[mt][2], a[mt][3],
                             bf[nt][0], bf[nt][1]);
        }
        __syncthreads();
    }

    #pragma unroll
    for (int nt = 0; nt < 4; nt++) {
        int c = col0 + warp_n * 32 + nt * 8 + t * 2;
        float b0 = bias ? bias[c]     : 0.f;
        float b1 = bias ? bias[c + 1] : 0.f;
        #pragma unroll
        for (int mt = 0; mt < 4; mt++) {
            int r = row0 + warp_m * 64 + mt * 16 + g;
            #pragma unroll
            for (int half = 0; half < 2; half++) {
                int rr = r + half * 8;
                if (rr < M) {
                    float v0 = acc[mt][nt][half * 2 + 0] * alpha + b0;
                    float v1 = acc[mt][nt][half * 2 + 1] * alpha + b1;
                    if (rndo) { v0 = roundtf32(v0); v1 = roundtf32(v1); }
                    float* cp = Cc + (size_t)rr * ldc + c;
                    cp[0] = v0;
                    cp[1] = v1;
                }
            }
        }
    }
}

// ======================================================================
// Space attention on tensor cores; Q/K fragments via ldmatrix.
// Smem words: Qs 128x68, Ks 208x68 (rows>=196 zero), Vs 200x72.
// ======================================================================
#define SAT_SMEM_BYTES ((128*68 + 208*68 + 200*72) * 4)

__global__ __launch_bounds__(256) void space_attn_mma()
{
    extern __shared__ uint32_t ssm[];
    uint32_t* Qs = ssm;                  // [128][68]
    uint32_t* Ks = ssm + 128 * 68;       // [208][68]
    uint32_t* Vs = Ks + 208 * 68;        // [200][72]

    const int qt   = blockIdx.x;
    const int f    = blockIdx.y;
    const int bh   = blockIdx.z;
    const int b    = bh / H_;
    const int head = bh % H_;
    const int tid  = threadIdx.x;
    const int w    = tid >> 5;
    const int lane = tid & 31;
    const int g    = lane >> 2;
    const int t    = lane & 3;

    const float* base = g_qkv + (size_t)b * N_ * C3_;

    #pragma unroll
    for (int i = 0; i < 8; i++) {
        int idx = tid + i * 256;
        int r   = idx >> 4;
        int cf  = (idx & 15) * 4;
        int sq  = qt * 128 + r;
        float4 v = make_float4(0.f, 0.f, 0.f, 0.f);
        if (sq < S_)
            v = *(const float4*)(base + (size_t)(1 + sq) * C3_ + head * D_ + cf);
        uint32_t* d = &Qs[r * 68 + cf];
        d[0] = f2tf32(v.x); d[1] = f2tf32(v.y);
        d[2] = f2tf32(v.z); d[3] = f2tf32(v.w);
    }
    // K rows 0..207 (>=196 zero), V rows 0..199 (>=196 zero)
    for (int idx = tid; idx < 208 * 16; idx += 256) {
        int r  = idx >> 4;
        int cf = (idx & 15) * 4;
        float4 kv = make_float4(0.f, 0.f, 0.f, 0.f);
        float4 vv = make_float4(0.f, 0.f, 0.f, 0.f);
        if (r < P_) {
            const float* row = base + (size_t)(1 + f * P_ + r) * C3_ + head * D_ + cf;
            kv = *(const float4*)(row + C_);
            vv = *(const float4*)(row + 2 * C_);
        }
        uint32_t* dk = &Ks[r * 68 + cf];
        dk[0] = f2tf32(kv.x); dk[1] = f2tf32(kv.y);
        dk[2] = f2tf32(kv.z); dk[3] = f2tf32(kv.w);
        if (r < 200) {
            uint32_t* dv = &Vs[r * 72 + cf];
            dv[0] = f2tf32(vv.x); dv[1] = f2tf32(vv.y);
            dv[2] = f2tf32(vv.z); dv[3] = f2tf32(vv.w);
        }
    }
    __syncthreads();

    const int q0 = w * 16;
    if (qt * 128 + q0 >= S_) return;

    const int lrow = lane & 15;
    const int lcol = (lane >> 4) * 4;

    // ---- Q fragments via ldmatrix (8 x4-loads) ----
    const uint32_t q_addr0 = (uint32_t)__cvta_generic_to_shared(Qs) +
        (uint32_t)(((q0 + lrow) * 68 + lcol) * 4);
    uint32_t qa[8][4];
    #pragma unroll
    for (int kk = 0; kk < 8; kk++)
        ldsm_x4(qa[kk][0], qa[kk][1], qa[kk][2], qa[kk][3], q_addr0 + kk * 32);

    // ---- scores: 13 nt-pairs, K-frags via ldmatrix (2 nt per x4) ----
    const uint32_t k_addr0 = (uint32_t)__cvta_generic_to_shared(Ks) +
        (uint32_t)((lrow * 68 + lcol) * 4);
    float s[26][4];
    #pragma unroll
    for (int np = 0; np < 13; np++) {
        float* sa = s[2 * np];
        float* sb = s[2 * np + 1];
        sa[0] = sa[1] = sa[2] = sa[3] = 0.f;
        sb[0] = sb[1] = sb[2] = sb[3] = 0.f;
        #pragma unroll
        for (int kk = 0; kk < 8; kk++) {
            uint32_t k0, k1, k2, k3;
            ldsm_x4(k0, k1, k2, k3, k_addr0 + (uint32_t)((np * 16 * 68) * 4 + kk * 32));
            mma_tf32(sa, qa[kk][0], qa[kk][1], qa[kk][2], qa[kk][3], k0, k2);
            mma_tf32(sb, qa[kk][0], qa[kk][1], qa[kk][2], qa[kk][3], k1, k3);
        }
    }
    #pragma unroll
    for (int nt = 0; nt < 25; nt++) {
        s[nt][0] *= SCALE; s[nt][1] *= SCALE;
        s[nt][2] *= SCALE; s[nt][3] *= SCALE;
    }
    if (t >= 2) { s[24][0] = s[24][1] = s[24][2] = s[24][3] = -1e30f; }

    float mlo = -1e30f, mhi = -1e30f;
    #pragma unroll
    for (int nt = 0; nt < 25; nt++) {
        mlo = fmaxf(mlo, fmaxf(s[nt][0], s[nt][1]));
        mhi = fmaxf(mhi, fmaxf(s[nt][2], s[nt][3]));
    }
    mlo = fmaxf(mlo, __shfl_xor_sync(0xffffffffu, mlo, 1));
    mlo = fmaxf(mlo, __shfl_xor_sync(0xffffffffu, mlo, 2));
    mhi = fmaxf(mhi, __shfl_xor_sync(0xffffffffu, mhi, 1));
    mhi = fmaxf(mhi, __shfl_xor_sync(0xffffffffu, mhi, 2));

    float slo = 0.f, shi = 0.f;
    #pragma unroll
    for (int nt = 0; nt < 25; nt++) {
        s[nt][0] = __expf(s[nt][0] - mlo); slo += s[nt][0];
        s[nt][1] = __expf(s[nt][1] - mlo); slo += s[nt][1];
        s[nt][2] = __expf(s[nt][2] - mhi); shi += s[nt][2];
        s[nt][3] = __expf(s[nt][3] - mhi); shi += s[nt][3];
    }
    slo += __shfl_xor_sync(0xffffffffu, slo, 1);
    slo += __shfl_xor_sync(0xffffffffu, slo, 2);
    shi += __shfl_xor_sync(0xffffffffu, shi, 1);
    shi += __shfl_xor_sync(0xffffffffu, shi, 2);
    float rlo = 1.f / slo, rhi = 1.f / shi;
    #pragma unroll
    for (int nt = 0; nt < 25; nt++) {
        s[nt][0] *= rlo; s[nt][1] *= rlo;
        s[nt][2] *= rhi; s[nt][3] *= rhi;
    }

    float o[8][4];
    #pragma unroll
    for (int n = 0; n < 8; n++)
        o[n][0] = o[n][1] = o[n][2] = o[n][3] = 0.f;

    const int src0 = (lane & ~3) | (t >> 1);
    const int src1 = src0 | 2;

    #pragma unroll
    for (int kk = 0; kk < 25; kk++) {
        float x0 = __shfl_sync(0xffffffffu, s[kk][0], src0);
        float x1 = __shfl_sync(0xffffffffu, s[kk][1], src0);
        float x2 = __shfl_sync(0xffffffffu, s[kk][2], src0);
        float x3 = __shfl_sync(0xffffffffu, s[kk][3], src0);
        float y0 = __shfl_sync(0xffffffffu, s[kk][0], src1);
        float y1 = __shfl_sync(0xffffffffu, s[kk][1], src1);
        float y2 = __shfl_sync(0xffffffffu, s[kk][2], src1);
        float y3 = __shfl_sync(0xffffffffu, s[kk][3], src1);
        uint32_t pa0 = f2tf32((t & 1) ? x1 : x0);
        uint32_t pa1 = f2tf32((t & 1) ? x3 : x2);
        uint32_t pa2 = f2tf32((t & 1) ? y1 : y0);
        uint32_t pa3 = f2tf32((t & 1) ? y3 : y2);
        #pragma unroll
        for (int n = 0; n < 8; n++) {
            uint32_t b0 = Vs[(8 * kk + t) * 72 + 8 * n + g];
            uint32_t b1 = Vs[(8 * kk + t + 4) * 72 + 8 * n + g];
            mma_tf32(o[n], pa0, pa1, pa2, pa3, b0, b1);
        }
    }

    const int r1 = qt * 128 + q0 + g;
    const int r2 = r1 + 8;
    #pragma unroll
    for (int n = 0; n < 8; n++) {
        int c = head * D_ + 8 * n + 2 * t;
        float* p1 = g_traj + ((size_t)(b * S_ + r1) * F_ + f) * C_ + c;
        p1[0] = roundtf32(o[n][0]); p1[1] = roundtf32(o[n][1]);
        float* p2 = g_traj + ((size_t)(b * S_ + r2) * F_ + f) * C_ + c;
        p2[0] = roundtf32(o[n][2]); p2[1] = roundtf32(o[n][3]);
    }
}

// ======================================================================
// CLS attention (unchanged)
// ======================================================================
__global__ __launch_bounds__(256) void cls_attn_kernel()
{
    __shared__ float sims[N_];
    __shared__ float q0s[64];
    __shared__ float red[9];

    const int bh   = blockIdx.x;
    const int b    = bh / H_;
    const int head = bh % H_;
    const int tid  = threadIdx.x;
    const int w    = tid >> 5;
    const int lane = tid & 31;

    const float* base = g_qkv + (size_t)b * N_ * C3_;

    if (tid < 64) q0s[tid] = base[head * D_ + tid];
    __syncthreads();

    for (int j = tid; j < N_; j += 256) {
        const float* kr = base + (size_t)j * C3_ + C_ + head * D_;
        float dsum = 0.f;
        #pragma unroll
        for (int di = 0; di < 64; di += 4) {
            float4 kv = *(const float4*)(kr + di);
            dsum += q0s[di] * kv.x + q0s[di + 1] * kv.y
                  + q0s[di + 2] * kv.z + q0s[di + 3] * kv.w;
        }
        sims[j] = dsum * SCALE;
    }
    __syncthreads();

    float m = -1e30f;
    for (int j = tid; j < N_; j += 256) m = fmaxf(m, sims[j]);
    #pragma unroll
    for (int off = 16; off; off >>= 1) m = fmaxf(m, __shfl_xor_sync(0xffffffffu, m, off));
    if (lane == 0) red[w] = m;
    __syncthreads();
    if (tid == 0) {
        float mm = red[0];
        #pragma unroll
        for (int i = 1; i < 8; i++) mm = fmaxf(mm, red[i]);
        red[8] = mm;
    }
    __syncthreads();
    const float M = red[8];
    __syncthreads();

    float ls = 0.f;
    for (int j = tid; j < N_; j += 256) {
        float p = __expf(sims[j] - M);
        sims[j] = p;
        ls += p;
    }
    #pragma unroll
    for (int off = 16; off; off >>= 1) ls += __shfl_xor_sync(0xffffffffu, ls, off);
    if (lane == 0) red[w] = ls;
    __syncthreads();
    if (tid == 0) {
        float ss = 0.f;
        #pragma unroll
        for (int i = 0; i < 8; i++) ss += red[i];
        red[8] = ss;
    }
    __syncthreads();
    const float SUM = red[8];

    if (tid < 64) {
        float acc = 0.f;
        const float* vcol = base + 2 * C_ + head * D_ + tid;
        #pragma unroll 4
        for (int j = 0; j < N_; j++)
            acc += sims[j] * vcol[(size_t)j * C3_];
        g_attin[(size_t)b * N_ * C_ + head * D_ + tid] = roundtf32(acc / SUM);
    }
}

// ======================================================================
// Final frame attention (unchanged from R12)
// ======================================================================
__global__ __launch_bounds__(256) void final_attn2_kernel(float* __restrict__ attn_out)
{
    __shared__ float trajs[F_ * C_];
    __shared__ float lg[H_ * F_];
    __shared__ float pw[H_ * F_];

    const int bs   = blockIdx.x;
    const int b    = bs / S_;
    const int s    = bs % S_;
    const int tid  = threadIdx.x;
    const int w    = tid >> 5;
    const int lane = tid & 31;

    const float* tsrc = g_traj + (size_t)bs * F_ * C_;
    #pragma unroll
    for (int i = 0; i < 6; i++) {
        int idx = (tid + i * 256) * 4;
        *(float4*)(trajs + idx) = *(const float4*)(tsrc + idx);
    }
    __syncthreads();

    const float4* ub = (const float4*)(g_u + (size_t)bs * H_ * C_);
    for (int pi = w; pi < H_ * F_; pi += 8) {
        int h = pi >> 3;
        int f = pi & 7;
        const float4* up = ub + h * (C_ / 4);
        const float4* tp = (const float4*)(trajs + f * C_);
        float acc = 0.f;
        #pragma unroll
        for (int j = 0; j < C_ / 128; j++) {
            float4 uv = up[lane + 32 * j];
            float4 tv = tp[lane + 32 * j];
            acc += uv.x * tv.x + uv.y * tv.y + uv.z * tv.z + uv.w * tv.w;
        }
        #pragma unroll
        for (int off = 16; off; off >>= 1)
            acc += __shfl_xor_sync(0xffffffffu, acc, off);
        if (lane == 0) lg[pi] = acc;
    }
    __syncthreads();

    if (tid < H_) {
        float m = lg[tid * F_];
        #pragma unroll
        for (int f = 1; f < F_; f++) m = fmaxf(m, lg[tid * F_ + f]);
        float p[F_], sum = 0.f;
        #pragma unroll
        for (int f = 0; f < F_; f++) { p[f] = __expf(lg[tid * F_ + f] - m); sum += p[f]; }
        float inv = 1.f / sum;
        float* ap = attn_out + (((size_t)b * H_ + tid) * S_ + s) * F_;
        #pragma unroll
        for (int f = 0; f < F_; f++) {
            float v = p[f] * inv;
            pw[tid * F_ + f] = v;
            ap[f] = v;
        }
    }
    __syncthreads();

    float* op = g_attin + ((size_t)b * N_ + 1 + s) * C_;
    #pragma unroll
    for (int i = 0; i < 3; i++) {
        int c = tid + i * 256;
        int h = c >> 6;
        float acc = 0.f;
        #pragma unroll
        for (int f = 0; f < F_; f++)
            acc += pw[h * F_ + f] * trajs[f * C_ + c];
        op[c] = roundtf32(acc);
    }
}

// ======================================================================
// Host launcher — fork/join stream overlap (graph-capture safe)
// ======================================================================
extern "C" void kernel_launch(void* const* d_in, const int* in_sizes, int n_in,
                              void* d_out, int out_size)
{
    const float* x      = (const float*)d_in[0];
    const float* W_qkv  = (const float*)d_in[1];
    const float* W_pq   = (const float*)d_in[2];
    const float* W_pkv  = (const float*)d_in[3];
    const float* W_proj = (const float*)d_in[4];
    const float* b_proj = (const float*)d_in[5];

    float* out  = (float*)d_out;
    float* attn = out + (size_t)B_ * N_ * C_;

    float *qkv, *traj, *q2, *u, *attin;
    float *xr, *wqkvr, *wpqr, *wkT, *wprojr;
    cudaGetSymbolAddress((void**)&qkv,   g_qkv);
    cudaGetSymbolAddress((void**)&traj,  g_traj);
    cudaGetSymbolAddress((void**)&q2,    g_q2);
    cudaGetSymbolAddress((void**)&u,     g_u);
    cudaGetSymbolAddress((void**)&attin, g_attin);
    cudaGetSymbolAddress((void**)&xr,     g_xr);
    cudaGetSymbolAddress((void**)&wqkvr,  g_wqkvr);
    cudaGetSymbolAddress((void**)&wpqr,   g_wpqr);
    cudaGetSymbolAddress((void**)&wkT,    g_wkT);
    cudaGetSymbolAddress((void**)&wprojr, g_wprojr);

    cudaFuncSetAttribute(gemm_tf32_db,
                         cudaFuncAttributeMaxDynamicSharedMemorySize, GEMM_SMEM_BYTES);
    cudaFuncSetAttribute(space_attn_mma,
                         cudaFuncAttributeMaxDynamicSharedMemorySize, SAT_SMEM_BYTES);

    static cudaStream_t s2 = nullptr;
    static cudaEvent_t e_fork = nullptr, e_prep = nullptr, e_qkv = nullptr, e_cls = nullptr;
    if (!s2) {
        cudaStreamCreateWithFlags(&s2, cudaStreamNonBlocking);
        cudaEventCreateWithFlags(&e_fork, cudaEventDisableTiming);
        cudaEventCreateWithFlags(&e_prep, cudaEventDisableTiming);
        cudaEventCreateWithFlags(&e_qkv,  cudaEventDisableTiming);
        cudaEventCreateWithFlags(&e_cls,  cudaEventDisableTiming);
    }

    cudaEventRecord(e_fork, 0);
    cudaStreamWaitEvent(s2, e_fork, 0);

    round_tf32_kernel<<<(C_*C_/4 + 255)/256, 256, 0, s2>>>(W_pq,   wpqr,   C_*C_);
    round_tf32_kernel<<<(C_*C_/4 + 255)/256, 256, 0, s2>>>(W_proj, wprojr, C_*C_);
    transpose_round_kernel<<<dim3(C_/32, C_/32), dim3(32, 8), 0, s2>>>(W_pkv, wkT);
    cudaEventRecord(e_prep, s2);

    round_tf32_kernel<<<(B_*N_*C_/4 + 255)/256, 256>>>(x,     xr,    B_*N_*C_);
    round_tf32_kernel<<<(C_*C3_ /4 + 255)/256, 256>>>(W_qkv, wqkvr, C_*C3_);
    gemm_tf32_db<<<dim3(C3_/128, (B_*N_ + 127)/128), 256, GEMM_SMEM_BYTES>>>(
        xr, C_, wqkvr, C3_, qkv, C3_, B_*N_, C_, 1.f, nullptr, 0, 0, 0, 0);
    cudaEventRecord(e_qkv, 0);

    cudaStreamWaitEvent(s2, e_qkv, 0);
    cls_attn_kernel<<<B_ * H_, 256, 0, s2>>>();
    cudaEventRecord(e_cls, s2);

    space_attn_mma<<<dim3(13, F_, B_ * H_), 256, SAT_SMEM_BYTES>>>();

    cudaStreamWaitEvent(0, e_prep, 0);
    gemm_tf32_db<<<dim3(C_/128, (BS_ + 127)/128), 256, GEMM_SMEM_BYTES>>>(
        traj, 0, wpqr, C_, q2, C_, BS_, C_, SCALE, nullptr, 1 | 2, 0, 0, 0);

    gemm_tf32_db<<<dim3(C_/128, (BS_ + 127)/128, H_), 256, GEMM_SMEM_BYTES>>>(
        q2, C_, wkT, C_, u, H_ * C_, BS_, D_, 1.f, nullptr, 0,
        D_, (size_t)D_ * C_, (size_t)C_);

    final_attn2_kernel<<<BS_, 256>>>(attn);

    cudaStreamWaitEvent(0, e_cls, 0);
    gemm_tf32_db<<<dim3(C_/128, (B_*N_ + 127)/128), 256, GEMM_SMEM_BYTES>>>(
        attin, C_, wprojr, C_, out, C_, B_*N_, C_, 1.f, b_proj, 0, 0, 0, 0);
}

// round 16
// speedup vs baseline: 1.1083x; 1.1083x over previous
#include <cuda_runtime.h>
#include <cstdint>
#include <cstddef>

// ---------------- problem constants ----------------
#define B_   2
#define N_   1569
#define C_   768
#define H_   12
#define D_   64
#define P_   196
#define F_   8
#define S_   1568          // F_*P_ = N_-1
#define C3_  2304          // 3*C_
#define BS_  (B_*S_)       // 3136
#define SCALE 0.125f       // d^-0.5 = 1/8

// ---------------- scratch (device globals) ----------------
__device__ float g_qkv  [B_*N_*C3_];     // tf32-rounded (GEMM epilogue)
__device__ float g_traj [B_*S_*F_*C_];   // tf32-rounded
__device__ float g_q2   [B_*S_*C_];      // tf32-rounded
__device__ float g_u    [BS_*H_*C_];     // u[bs][h*C+c]
__device__ float g_attin[B_*N_*C_];      // tf32-rounded
__device__ float g_xr    [B_*N_*C_];
__device__ float g_wqkvr [C_*C3_];
__device__ float g_wpqr  [C_*C_];
__device__ float g_wkT   [C_*C_];
__device__ float g_wprojr[C_*C_];

// ---------------- helpers ----------------
__device__ __forceinline__ uint32_t f2tf32(float f) {
    uint32_t o;
    asm("cvt.rna.tf32.f32 %0, %1;" : "=r"(o) : "f"(f));
    return o;
}
__device__ __forceinline__ float roundtf32(float f) {
    return __uint_as_float(f2tf32(f));
}
__device__ __forceinline__ void cp16(void* dst, const void* src, bool p) {
    uint32_t d = (uint32_t)__cvta_generic_to_shared(dst);
    int sz = p ? 16 : 0;
    asm volatile("cp.async.ca.shared.global [%0], [%1], 16, %2;"
                 :: "r"(d), "l"(src), "r"(sz));
}
__device__ __forceinline__ void cp_commit() {
    asm volatile("cp.async.commit_group;");
}
__device__ __forceinline__ void mma_tf32(float* c,
    uint32_t a0, uint32_t a1, uint32_t a2, uint32_t a3,
    uint32_t b0, uint32_t b1)
{
    asm volatile(
        "mma.sync.aligned.m16n8k8.row.col.f32.tf32.tf32.f32 "
        "{%0,%1,%2,%3}, {%4,%5,%6,%7}, {%8,%9}, {%0,%1,%2,%3};"
        : "+f"(c[0]), "+f"(c[1]), "+f"(c[2]), "+f"(c[3])
        : "r"(a0), "r"(a1), "r"(a2), "r"(a3), "r"(b0), "r"(b1));
}
__device__ __forceinline__ void ldsm_x4(uint32_t& r0, uint32_t& r1,
                                        uint32_t& r2, uint32_t& r3, uint32_t addr)
{
    asm volatile("ldmatrix.sync.aligned.m8n8.x4.shared.b16 {%0,%1,%2,%3}, [%4];"
                 : "=r"(r0), "=r"(r1), "=r"(r2), "=r"(r3) : "r"(addr));
}

// ======================================================================
// Pre-pass: round to tf32 (rna). n % 4 == 0.
// ======================================================================
__global__ __launch_bounds__(256) void round_tf32_kernel(
    const float* __restrict__ src, float* __restrict__ dst, int n)
{
    int i = (blockIdx.x * 256 + threadIdx.x) * 4;
    if (i >= n) return;
    float4 v = *(const float4*)(src + i);
    v.x = roundtf32(v.x); v.y = roundtf32(v.y);
    v.z = roundtf32(v.z); v.w = roundtf32(v.w);
    *(float4*)(dst + i) = v;
}

// ======================================================================
// Transpose + round: WkT[c'][c] = W_pkv[c][c'].
// ======================================================================
__global__ __launch_bounds__(256) void transpose_round_kernel(
    const float* __restrict__ src, float* __restrict__ dst)
{
    __shared__ float tile[32][33];
    int x0 = blockIdx.x * 32;
    int y0 = blockIdx.y * 32;
    #pragma unroll
    for (int i = 0; i < 4; i++) {
        int y = y0 + threadIdx.y + i * 8;
        tile[threadIdx.y + i * 8][threadIdx.x] =
            roundtf32(src[(size_t)y * (2 * C_) + x0 + threadIdx.x]);
    }
    __syncthreads();
    #pragma unroll
    for (int i = 0; i < 4; i++) {
        int yo = x0 + threadIdx.y + i * 8;
        dst[(size_t)yo * C_ + y0 + threadIdx.x] =
            tile[threadIdx.x][threadIdx.y + i * 8];
    }
}

// ======================================================================
// TF32 GEMM, cp.async double buffered; A-fragments via ldmatrix.x4.
// flags bit0: diag A-gather; bit1: round output to tf32.
// ======================================================================
#define GEMM_SMEM_BYTES ((2*128*36 + 2*32*136) * 4)

__global__ __launch_bounds__(256, 2) void gemm_tf32_db(
    const float* __restrict__ A, int lda,
    const float* __restrict__ Bw, int ldb,
    float* __restrict__ Cc, int ldc,
    int M, int K, float alpha, const float* __restrict__ bias, int flags,
    int zsa, size_t zsb, size_t zsc)
{
    extern __shared__ float gsm[];
    float* As = gsm;                 // [2][128*36]
    float* Bs = gsm + 2 * 128 * 36;  // [2][32*136]

    A  += (size_t)blockIdx.z * zsa;
    Bw += (size_t)blockIdx.z * zsb;
    Cc += (size_t)blockIdx.z * zsc;

    const int tid    = threadIdx.x;
    const int warp   = tid >> 5;
    const int lane   = tid & 31;
    const int g      = lane >> 2;
    const int t      = lane & 3;
    const int warp_m = warp >> 2;
    const int warp_n = warp & 3;
    const int row0   = blockIdx.y * 128;
    const int col0   = blockIdx.x * 128;
    const bool diag  = flags & 1;
    const bool rndo  = flags & 2;

    const uint32_t a_smem0 = (uint32_t)__cvta_generic_to_shared(As);
    const int arow = lane & 15;
    const int acol = (lane >> 4) * 4;

    float acc[4][4][4];
    #pragma unroll
    for (int mt = 0; mt < 4; mt++)
        #pragma unroll
        for (int nt = 0; nt < 4; nt++)
            #pragma unroll
            for (int r = 0; r < 4; r++) acc[mt][nt][r] = 0.f;

    const int ntiles = K / 32;

    auto issue_tile = [&](int buf, int k0) {
        float* Ab = As + buf * 128 * 36;
        float* Bb = Bs + buf * 32 * 136;
        #pragma unroll
        for (int i = 0; i < 4; i++) {
            int idx = tid + i * 256;
            int r   = idx >> 3;
            int c   = (idx & 7) * 4;
            int gr  = row0 + r;
            const float* src;
            if (diag) {
                int s = gr % S_;
                src = A + ((size_t)gr * F_ + (s / P_)) * C_ + k0 + c;
            } else {
                src = A + (size_t)gr * lda + k0 + c;
            }
            cp16(Ab + r * 36 + c, src, gr < M);
        }
        #pragma unroll
        for (int i = 0; i < 4; i++) {
            int idx = tid + i * 256;
            int r   = idx >> 5;
            int c   = (idx & 31) * 4;
            cp16(Bb + r * 136 + c, Bw + (size_t)(k0 + r) * ldb + col0 + c, true);
        }
        cp_commit();
    };

    issue_tile(0, 0);

    for (int kt = 0; kt < ntiles; kt++) {
        int cur = kt & 1;
        if (kt + 1 < ntiles) {
            issue_tile(cur ^ 1, (kt + 1) * 32);
            asm volatile("cp.async.wait_group 1;");
        } else {
            asm volatile("cp.async.wait_group 0;");
        }
        __syncthreads();

        const uint32_t* Bb = (const uint32_t*)(Bs + cur * 32 * 136);
        const uint32_t a_base = a_smem0 + (uint32_t)(cur * 128 * 36) * 4u;

        #pragma unroll
        for (int kk = 0; kk < 32; kk += 8) {
            uint32_t a[4][4], bf[4][2];
            #pragma unroll
            for (int mt = 0; mt < 4; mt++) {
                uint32_t addr = a_base +
                    (uint32_t)(((warp_m * 64 + mt * 16 + arow) * 36 + acol + kk) * 4);
                ldsm_x4(a[mt][0], a[mt][1], a[mt][2], a[mt][3], addr);
            }
            #pragma unroll
            for (int nt = 0; nt < 4; nt++) {
                int c = warp_n * 32 + nt * 8 + g;
                const uint32_t* p = &Bb[(kk + t) * 136 + c];
                bf[nt][0] = p[0];
                bf[nt][1] = p[4 * 136];
            }
            #pragma unroll
            for (int mt = 0; mt < 4; mt++)
                #pragma unroll
                for (int nt = 0; nt < 4; nt++)
                    mma_tf32(acc[mt][nt], a[mt][0], a[mt][1], a[mt][2], a[mt][3],
                             bf[nt][0], bf[nt][1]);
        }
        __syncthreads();
    }

    #pragma unroll
    for (int nt = 0; nt < 4; nt++) {
        int c = col0 + warp_n * 32 + nt * 8 + t * 2;
        float b0 = bias ? bias[c]     : 0.f;
        float b1 = bias ? bias[c + 1] : 0.f;
        #pragma unroll
        for (int mt = 0; mt < 4; mt++) {
            int r = row0 + warp_m * 64 + mt * 16 + g;
            #pragma unroll
            for (int half = 0; half < 2; half++) {
                int rr = r + half * 8;
                if (rr < M) {
                    float v0 = acc[mt][nt][half * 2 + 0] * alpha + b0;
                    float v1 = acc[mt][nt][half * 2 + 1] * alpha + b1;
                    if (rndo) { v0 = roundtf32(v0); v1 = roundtf32(v1); }
                    float* cp = Cc + (size_t)rr * ldc + c;
                    cp[0] = v0;
                    cp[1] = v1;
                }
            }
        }
    }
}

// ======================================================================
// Space attention, pipelined: block = (q-tile, bh), loop over frames.
// qkv pre-rounded -> cp.async direct staging (no cvt phase).
// Smem: Qs[128][68], K0/K1[208][68] (rows>=196 zero), Vs[200][72].
// ======================================================================
#define SAP_SMEM_BYTES ((128*68 + 2*208*68 + 200*72) * 4)   // 205568

__global__ __launch_bounds__(256) void space_attn_pipe()
{
    extern __shared__ uint32_t ssm[];
    uint32_t* Qs = ssm;                   // [128][68]
    uint32_t* K0 = ssm + 128 * 68;        // [208][68]
    uint32_t* K1 = K0 + 208 * 68;         // [208][68]
    uint32_t* Vs = K1 + 208 * 68;         // [200][72]

    const int qt   = blockIdx.x;          // 0..12
    const int bh   = blockIdx.y;          // 0..23
    const int b    = bh / H_;
    const int head = bh % H_;
    const int tid  = threadIdx.x;
    const int w    = tid >> 5;
    const int lane = tid & 31;
    const int g    = lane >> 2;
    const int t    = lane & 3;
    const int lrow = lane & 15;
    const int lcol = (lane >> 4) * 4;

    const float* base = g_qkv + (size_t)b * N_ * C3_;   // tf32-rounded

    // zero pad rows (written once; cp.async only touches rows < 196)
    for (int i = tid; i < 12 * 68; i += 256) { K0[196 * 68 + i] = 0; K1[196 * 68 + i] = 0; }
    for (int i = tid; i < 4 * 72; i += 256) Vs[196 * 72 + i] = 0;

    auto issue_k = [&](int f, uint32_t* dst) {
        for (int idx = tid; idx < P_ * 16; idx += 256) {
            int r  = idx >> 4;
            int cf = (idx & 15) * 4;
            cp16(dst + r * 68 + cf,
                 base + (size_t)(1 + f * P_ + r) * C3_ + C_ + head * D_ + cf, true);
        }
    };
    auto issue_v = [&](int f) {
        for (int idx = tid; idx < P_ * 16; idx += 256) {
            int r  = idx >> 4;
            int cf = (idx & 15) * 4;
            cp16(Vs + r * 72 + cf,
                 base + (size_t)(1 + f * P_ + r) * C3_ + 2 * C_ + head * D_ + cf, true);
        }
    };

    // issue Q + K(0) + V(0) as one group
    #pragma unroll
    for (int i = 0; i < 8; i++) {
        int idx = tid + i * 256;
        int r   = idx >> 4;
        int cf  = (idx & 15) * 4;
        int sq  = qt * 128 + r;
        cp16(Qs + r * 68 + cf,
             base + (size_t)(1 + sq) * C3_ + head * D_ + cf, sq < S_);  // OOB -> zero fill
    }
    issue_k(0, K0);
    issue_v(0);
    cp_commit();
    asm volatile("cp.async.wait_group 0;");
    __syncthreads();

    // Q fragments (held in registers across all frames)
    const uint32_t q_addr0 = (uint32_t)__cvta_generic_to_shared(Qs) +
        (uint32_t)(((w * 16 + lrow) * 68 + lcol) * 4);
    uint32_t qa[8][4];
    #pragma unroll
    for (int kk = 0; kk < 8; kk++)
        ldsm_x4(qa[kk][0], qa[kk][1], qa[kk][2], qa[kk][3], q_addr0 + kk * 32);

    const int src0 = (lane & ~3) | (t >> 1);
    const int src1 = src0 | 2;
    const int r1g  = qt * 128 + w * 16 + g;   // output rows r1g, r1g+8

    int bufsel = 0;
    for (int f = 0; f < F_; f++) {
        uint32_t* Kc = bufsel ? K1 : K0;
        uint32_t* Kn = bufsel ? K0 : K1;
        if (f < 7) { issue_k(f + 1, Kn); cp_commit(); }

        // ---- scores from Kc ----
        const uint32_t k_base = (uint32_t)__cvta_generic_to_shared(Kc) +
            (uint32_t)((lrow * 68 + lcol) * 4);
        float s[26][4];
        #pragma unroll
        for (int np = 0; np < 13; np++) {
            float* sa = s[2 * np];
            float* sb = s[2 * np + 1];
            sa[0] = sa[1] = sa[2] = sa[3] = 0.f;
            sb[0] = sb[1] = sb[2] = sb[3] = 0.f;
            #pragma unroll
            for (int kk = 0; kk < 8; kk++) {
                uint32_t k0, k1, k2, k3;
                ldsm_x4(k0, k1, k2, k3,
                        k_base + (uint32_t)((np * 16 * 68) * 4 + kk * 32));
                mma_tf32(sa, qa[kk][0], qa[kk][1], qa[kk][2], qa[kk][3], k0, k2);
                mma_tf32(sb, qa[kk][0], qa[kk][1], qa[kk][2], qa[kk][3], k1, k3);
            }
        }
        #pragma unroll
        for (int nt = 0; nt < 25; nt++) {
            s[nt][0] *= SCALE; s[nt][1] *= SCALE;
            s[nt][2] *= SCALE; s[nt][3] *= SCALE;
        }
        if (t >= 2) { s[24][0] = s[24][1] = s[24][2] = s[24][3] = -1e30f; }

        float mlo = -1e30f, mhi = -1e30f;
        #pragma unroll
        for (int nt = 0; nt < 25; nt++) {
            mlo = fmaxf(mlo, fmaxf(s[nt][0], s[nt][1]));
            mhi = fmaxf(mhi, fmaxf(s[nt][2], s[nt][3]));
        }
        mlo = fmaxf(mlo, __shfl_xor_sync(0xffffffffu, mlo, 1));
        mlo = fmaxf(mlo, __shfl_xor_sync(0xffffffffu, mlo, 2));
        mhi = fmaxf(mhi, __shfl_xor_sync(0xffffffffu, mhi, 1));
        mhi = fmaxf(mhi, __shfl_xor_sync(0xffffffffu, mhi, 2));

        float slo = 0.f, shi = 0.f;
        #pragma unroll
        for (int nt = 0; nt < 25; nt++) {
            s[nt][0] = __expf(s[nt][0] - mlo); slo += s[nt][0];
            s[nt][1] = __expf(s[nt][1] - mlo); slo += s[nt][1];
            s[nt][2] = __expf(s[nt][2] - mhi); shi += s[nt][2];
            s[nt][3] = __expf(s[nt][3] - mhi); shi += s[nt][3];
        }
        slo += __shfl_xor_sync(0xffffffffu, slo, 1);
        slo += __shfl_xor_sync(0xffffffffu, slo, 2);
        shi += __shfl_xor_sync(0xffffffffu, shi, 1);
        shi += __shfl_xor_sync(0xffffffffu, shi, 2);
        float rlo = 1.f / slo, rhi = 1.f / shi;
        #pragma unroll
        for (int nt = 0; nt < 25; nt++) {
            s[nt][0] *= rlo; s[nt][1] *= rlo;
            s[nt][2] *= rhi; s[nt][3] *= rhi;
        }

        // V(f) complete (K(f+1) may still be in flight)
        if (f < 7) asm volatile("cp.async.wait_group 1;");
        else       asm volatile("cp.async.wait_group 0;");
        __syncthreads();

        // ---- out = P @ V ----
        float o[8][4];
        #pragma unroll
        for (int n = 0; n < 8; n++)
            o[n][0] = o[n][1] = o[n][2] = o[n][3] = 0.f;

        #pragma unroll
        for (int kk = 0; kk < 25; kk++) {
            float x0 = __shfl_sync(0xffffffffu, s[kk][0], src0);
            float x1 = __shfl_sync(0xffffffffu, s[kk][1], src0);
            float x2 = __shfl_sync(0xffffffffu, s[kk][2], src0);
            float x3 = __shfl_sync(0xffffffffu, s[kk][3], src0);
            float y0 = __shfl_sync(0xffffffffu, s[kk][0], src1);
            float y1 = __shfl_sync(0xffffffffu, s[kk][1], src1);
            float y2 = __shfl_sync(0xffffffffu, s[kk][2], src1);
            float y3 = __shfl_sync(0xffffffffu, s[kk][3], src1);
            uint32_t pa0 = f2tf32((t & 1) ? x1 : x0);
            uint32_t pa1 = f2tf32((t & 1) ? x3 : x2);
            uint32_t pa2 = f2tf32((t & 1) ? y1 : y0);
            uint32_t pa3 = f2tf32((t & 1) ? y3 : y2);
            #pragma unroll
            for (int n = 0; n < 8; n++) {
                uint32_t b0 = Vs[(8 * kk + t) * 72 + 8 * n + g];
                uint32_t b1 = Vs[(8 * kk + t + 4) * 72 + 8 * n + g];
                mma_tf32(o[n], pa0, pa1, pa2, pa3, b0, b1);
            }
        }

        #pragma unroll
        for (int n = 0; n < 8; n++) {
            int c = head * D_ + 8 * n + 2 * t;
            if (r1g < S_) {
                float* p1 = g_traj + ((size_t)(b * S_ + r1g) * F_ + f) * C_ + c;
                p1[0] = roundtf32(o[n][0]); p1[1] = roundtf32(o[n][1]);
            }
            if (r1g + 8 < S_) {
                float* p2 = g_traj + ((size_t)(b * S_ + r1g + 8) * F_ + f) * C_ + c;
                p2[0] = roundtf32(o[n][2]); p2[1] = roundtf32(o[n][3]);
            }
        }
        __syncthreads();   // all warps done reading Vs and Kc

        if (f < 7) {
            issue_v(f + 1);
            cp_commit();
            asm volatile("cp.async.wait_group 1;");  // K(f+1) done; V(f+1) pending
            __syncthreads();
        }
        bufsel ^= 1;
    }
}

// ======================================================================
// CLS attention (unchanged; reads rounded qkv)
// ======================================================================
__global__ __launch_bounds__(256) void cls_attn_kernel()
{
    __shared__ float sims[N_];
    __shared__ float q0s[64];
    __shared__ float red[9];

    const int bh   = blockIdx.x;
    const int b    = bh / H_;
    const int head = bh % H_;
    const int tid  = threadIdx.x;
    const int w    = tid >> 5;
    const int lane = tid & 31;

    const float* base = g_qkv + (size_t)b * N_ * C3_;

    if (tid < 64) q0s[tid] = base[head * D_ + tid];
    __syncthreads();

    for (int j = tid; j < N_; j += 256) {
        const float* kr = base + (size_t)j * C3_ + C_ + head * D_;
        float dsum = 0.f;
        #pragma unroll
        for (int di = 0; di < 64; di += 4) {
            float4 kv = *(const float4*)(kr + di);
            dsum += q0s[di] * kv.x + q0s[di + 1] * kv.y
                  + q0s[di + 2] * kv.z + q0s[di + 3] * kv.w;
        }
        sims[j] = dsum * SCALE;
    }
    __syncthreads();

    float m = -1e30f;
    for (int j = tid; j < N_; j += 256) m = fmaxf(m, sims[j]);
    #pragma unroll
    for (int off = 16; off; off >>= 1) m = fmaxf(m, __shfl_xor_sync(0xffffffffu, m, off));
    if (lane == 0) red[w] = m;
    __syncthreads();
    if (tid == 0) {
        float mm = red[0];
        #pragma unroll
        for (int i = 1; i < 8; i++) mm = fmaxf(mm, red[i]);
        red[8] = mm;
    }
    __syncthreads();
    const float M = red[8];
    __syncthreads();

    float ls = 0.f;
    for (int j = tid; j < N_; j += 256) {
        float p = __expf(sims[j] - M);
        sims[j] = p;
        ls += p;
    }
    #pragma unroll
    for (int off = 16; off; off >>= 1) ls += __shfl_xor_sync(0xffffffffu, ls, off);
    if (lane == 0) red[w] = ls;
    __syncthreads();
    if (tid == 0) {
        float ss = 0.f;
        #pragma unroll
        for (int i = 0; i < 8; i++) ss += red[i];
        red[8] = ss;
    }
    __syncthreads();
    const float SUM = red[8];

    if (tid < 64) {
        float acc = 0.f;
        const float* vcol = base + 2 * C_ + head * D_ + tid;
        #pragma unroll 4
        for (int j = 0; j < N_; j++)
            acc += sims[j] * vcol[(size_t)j * C3_];
        g_attin[(size_t)b * N_ * C_ + head * D_ + tid] = roundtf32(acc / SUM);
    }
}

// ======================================================================
// Final frame attention (unchanged from R12)
// ======================================================================
__global__ __launch_bounds__(256) void final_attn2_kernel(float* __restrict__ attn_out)
{
    __shared__ float trajs[F_ * C_];
    __shared__ float lg[H_ * F_];
    __shared__ float pw[H_ * F_];

    const int bs   = blockIdx.x;
    const int b    = bs / S_;
    const int s    = bs % S_;
    const int tid  = threadIdx.x;
    const int w    = tid >> 5;
    const int lane = tid & 31;

    const float* tsrc = g_traj + (size_t)bs * F_ * C_;
    #pragma unroll
    for (int i = 0; i < 6; i++) {
        int idx = (tid + i * 256) * 4;
        *(float4*)(trajs + idx) = *(const float4*)(tsrc + idx);
    }
    __syncthreads();

    const float4* ub = (const float4*)(g_u + (size_t)bs * H_ * C_);
    for (int pi = w; pi < H_ * F_; pi += 8) {
        int h = pi >> 3;
        int f = pi & 7;
        const float4* up = ub + h * (C_ / 4);
        const float4* tp = (const float4*)(trajs + f * C_);
        float acc = 0.f;
        #pragma unroll
        for (int j = 0; j < C_ / 128; j++) {
            float4 uv = up[lane + 32 * j];
            float4 tv = tp[lane + 32 * j];
            acc += uv.x * tv.x + uv.y * tv.y + uv.z * tv.z + uv.w * tv.w;
        }
        #pragma unroll
        for (int off = 16; off; off >>= 1)
            acc += __shfl_xor_sync(0xffffffffu, acc, off);
        if (lane == 0) lg[pi] = acc;
    }
    __syncthreads();

    if (tid < H_) {
        float m = lg[tid * F_];
        #pragma unroll
        for (int f = 1; f < F_; f++) m = fmaxf(m, lg[tid * F_ + f]);
        float p[F_], sum = 0.f;
        #pragma unroll
        for (int f = 0; f < F_; f++) { p[f] = __expf(lg[tid * F_ + f] - m); sum += p[f]; }
        float inv = 1.f / sum;
        float* ap = attn_out + (((size_t)b * H_ + tid) * S_ + s) * F_;
        #pragma unroll
        for (int f = 0; f < F_; f++) {
            float v = p[f] * inv;
            pw[tid * F_ + f] = v;
            ap[f] = v;
        }
    }
    __syncthreads();

    float* op = g_attin + ((size_t)b * N_ + 1 + s) * C_;
    #pragma unroll
    for (int i = 0; i < 3; i++) {
        int c = tid + i * 256;
        int h = c >> 6;
        float acc = 0.f;
        #pragma unroll
        for (int f = 0; f < F_; f++)
            acc += pw[h * F_ + f] * trajs[f * C_ + c];
        op[c] = roundtf32(acc);
    }
}

// ======================================================================
// Host launcher — fork/join stream overlap (graph-capture safe)
// ======================================================================
extern "C" void kernel_launch(void* const* d_in, const int* in_sizes, int n_in,
                              void* d_out, int out_size)
{
    const float* x      = (const float*)d_in[0];
    const float* W_qkv  = (const float*)d_in[1];
    const float* W_pq   = (const float*)d_in[2];
    const float* W_pkv  = (const float*)d_in[3];
    const float* W_proj = (const float*)d_in[4];
    const float* b_proj = (const float*)d_in[5];

    float* out  = (float*)d_out;
    float* attn = out + (size_t)B_ * N_ * C_;

    float *qkv, *traj, *q2, *u, *attin;
    float *xr, *wqkvr, *wpqr, *wkT, *wprojr;
    cudaGetSymbolAddress((void**)&qkv,   g_qkv);
    cudaGetSymbolAddress((void**)&traj,  g_traj);
    cudaGetSymbolAddress((void**)&q2,    g_q2);
    cudaGetSymbolAddress((void**)&u,     g_u);
    cudaGetSymbolAddress((void**)&attin, g_attin);
    cudaGetSymbolAddress((void**)&xr,     g_xr);
    cudaGetSymbolAddress((void**)&wqkvr,  g_wqkvr);
    cudaGetSymbolAddress((void**)&wpqr,   g_wpqr);
    cudaGetSymbolAddress((void**)&wkT,    g_wkT);
    cudaGetSymbolAddress((void**)&wprojr, g_wprojr);

    cudaFuncSetAttribute(gemm_tf32_db,
                         cudaFuncAttributeMaxDynamicSharedMemorySize, GEMM_SMEM_BYTES);
    cudaFuncSetAttribute(space_attn_pipe,
                         cudaFuncAttributeMaxDynamicSharedMemorySize, SAP_SMEM_BYTES);

    static cudaStream_t s2 = nullptr;
    static cudaEvent_t e_fork = nullptr, e_prep = nullptr, e_qkv = nullptr, e_cls = nullptr;
    if (!s2) {
        cudaStreamCreateWithFlags(&s2, cudaStreamNonBlocking);
        cudaEventCreateWithFlags(&e_fork, cudaEventDisableTiming);
        cudaEventCreateWithFlags(&e_prep, cudaEventDisableTiming);
        cudaEventCreateWithFlags(&e_qkv,  cudaEventDisableTiming);
        cudaEventCreateWithFlags(&e_cls,  cudaEventDisableTiming);
    }

    cudaEventRecord(e_fork, 0);
    cudaStreamWaitEvent(s2, e_fork, 0);

    round_tf32_kernel<<<(C_*C_/4 + 255)/256, 256, 0, s2>>>(W_pq,   wpqr,   C_*C_);
    round_tf32_kernel<<<(C_*C_/4 + 255)/256, 256, 0, s2>>>(W_proj, wprojr, C_*C_);
    transpose_round_kernel<<<dim3(C_/32, C_/32), dim3(32, 8), 0, s2>>>(W_pkv, wkT);
    cudaEventRecord(e_prep, s2);

    round_tf32_kernel<<<(B_*N_*C_/4 + 255)/256, 256>>>(x,     xr,    B_*N_*C_);
    round_tf32_kernel<<<(C_*C3_ /4 + 255)/256, 256>>>(W_qkv, wqkvr, C_*C3_);
    // qkv = x @ W_qkv, rounded to tf32 in epilogue (feeds cp.async staging)
    gemm_tf32_db<<<dim3(C3_/128, (B_*N_ + 127)/128), 256, GEMM_SMEM_BYTES>>>(
        xr, C_, wqkvr, C3_, qkv, C3_, B_*N_, C_, 1.f, nullptr, 2, 0, 0, 0);
    cudaEventRecord(e_qkv, 0);

    cudaStreamWaitEvent(s2, e_qkv, 0);
    cls_attn_kernel<<<B_ * H_, 256, 0, s2>>>();
    cudaEventRecord(e_cls, s2);

    // space attention (pipelined, frames inside)
    space_attn_pipe<<<dim3(13, B_ * H_), 256, SAP_SMEM_BYTES>>>();

    cudaStreamWaitEvent(0, e_prep, 0);
    gemm_tf32_db<<<dim3(C_/128, (BS_ + 127)/128), 256, GEMM_SMEM_BYTES>>>(
        traj, 0, wpqr, C_, q2, C_, BS_, C_, SCALE, nullptr, 1 | 2, 0, 0, 0);

    gemm_tf32_db<<<dim3(C_/128, (BS_ + 127)/128, H_), 256, GEMM_SMEM_BYTES>>>(
        q2, C_, wkT, C_, u, H_ * C_, BS_, D_, 1.f, nullptr, 0,
        D_, (size_t)D_ * C_, (size_t)C_);

    final_attn2_kernel<<<BS_, 256>>>(attn);

    cudaStreamWaitEvent(0, e_cls, 0);
    gemm_tf32_db<<<dim3(C_/128, (B_*N_ + 127)/128), 256, GEMM_SMEM_BYTES>>>(
        attin, C_, wprojr, C_, out, C_, B_*N_, C_, 1.f, b_proj, 0, 0, 0, 0);
}